// round 8
// baseline (speedup 1.0000x reference)
#include <cuda_runtime.h>
#include <cfloat>

// 101-layer chain h <- relu(w*h + b), w > 0, collapses exactly to
//   f(x) = S * max(x, C) + O.
// Prefix triples (S, C, O) compose associatively:
//   (g o f): S = Sg*Sf,  C = max(Cf, (Cg - Of)/Sf),  O = Sg*Of + Og.
//
// R8: flat kernel, EIGHT float4 per thread (2048 float4 per block, 4096
// blocks), per-warp redundant shuffle scan, no barrier. All 8 loads are
// issued before the scan (MLP=8 in the scan shadow); scan ALU overhead per
// byte halves vs R7.

__global__ __launch_bounds__(256)
void fused_flat8_ws_kernel(const float4* __restrict__ x4,
                           float4* __restrict__ o4,
                           const float* __restrict__ w,
                           const float* __restrict__ b,
                           int n_layers, int n4, int n,
                           const float* __restrict__ x,
                           float* __restrict__ out) {
    const int tid  = threadIdx.x;
    const int lane = tid & 31;
    const int base = blockIdx.x * 2048 + tid;

    // Prefetch all eight elements FIRST: DRAM latency overlaps the scan.
    float4 v[8];
    bool ok[8];
    #pragma unroll
    for (int k = 0; k < 8; ++k) {
        const int idx = base + k * 256;
        ok[k] = (idx < n4);
        if (ok[k]) v[k] = x4[idx];
    }

    // ---- per-warp shuffle scan over up to 128 layers (no barrier) ----
    float S = 1.0f, C = -FLT_MAX, O = 0.0f;
    #pragma unroll
    for (int k = 0; k < 4; ++k) {
        const int idx = 4 * lane + k;             // independent loads
        if (idx < n_layers) {
            const float wi = w[idx];
            const float bi = b[idx];
            const float Cl = __fdividef(-bi, wi);
            C = fmaxf(C, __fdividef(Cl - O, S));
            S = wi * S;
            O = fmaf(wi, O, bi);
        }
    }
    #pragma unroll
    for (int d = 1; d < 32; d <<= 1) {
        const float Sp = __shfl_up_sync(0xffffffffu, S, d);
        const float Cp = __shfl_up_sync(0xffffffffu, C, d);
        const float Op = __shfl_up_sync(0xffffffffu, O, d);
        if (lane >= d) {
            C = fmaxf(Cp, __fdividef(C - Op, Sp));
            O = fmaf(S, Op, O);   // uses pre-update S
            S = S * Sp;
        }
    }
    // broadcast lane 31's inclusive result to the whole warp
    S = __shfl_sync(0xffffffffu, S, 31);
    C = __shfl_sync(0xffffffffu, C, 31);
    O = __shfl_sync(0xffffffffu, O, 31);

    #pragma unroll
    for (int k = 0; k < 8; ++k) {
        if (ok[k]) {
            float4 r;
            r.x = fmaf(S, fmaxf(v[k].x, C), O);
            r.y = fmaf(S, fmaxf(v[k].y, C), O);
            r.z = fmaf(S, fmaxf(v[k].z, C), O);
            r.w = fmaf(S, fmaxf(v[k].w, C), O);
            o4[base + k * 256] = r;
        }
    }

    // scalar tail (n % 4 != 0) — negligible
    if (blockIdx.x == 0 && tid == 0) {
        for (int j = n4 * 4; j < n; ++j) {
            out[j] = fmaf(S, fmaxf(x[j], C), O);
        }
    }
}

extern "C" void kernel_launch(void* const* d_in, const int* in_sizes, int n_in,
                              void* d_out, int out_size) {
    const float* x = (const float*)d_in[0];
    const float* w = (const float*)d_in[1];
    const float* b = (const float*)d_in[2];
    float* out = (float*)d_out;

    const int n        = in_sizes[0];
    const int n_layers = in_sizes[1];
    const int n4       = n / 4;

    const int threads = 256;
    const int blocks  = (n4 + 2047) / 2048;   // 8 float4 per thread

    fused_flat8_ws_kernel<<<blocks, threads>>>(
        (const float4*)x, (float4*)out, w, b, n_layers, n4, n, x, out);
}